// round 4
// baseline (speedup 1.0000x reference)
#include <cuda_runtime.h>
#include <cstdint>

#define NQ 4096            // 8 batches * 512 queries
#define THREADS 256

// Per-query precomputed [s, e) for each of the 3 tensors.
__device__ int2 g_se[3][NQ];

__global__ void precompute_se(const float* __restrict__ start,
                              const float* __restrict__ dur) {
    int q = blockIdx.x * blockDim.x + threadIdx.x;
    if (q >= NQ) return;
    const float st = start[q];
    const float du = dur[q];
    const float ratios[3] = {1.0f, 0.5f, 0.25f};
    const int   Ts[3]     = {16384, 8192, 4096};
#pragma unroll
    for (int t = 0; t < 3; t++) {
        // Match reference fp32 op order exactly.
        int s = (int)floorf(st * ratios[t]);
        if (s > Ts[t] - 1) s = Ts[t] - 1;
        int e = (int)ceilf((st + du + 1e-3f) * ratios[t]);
        if (e > Ts[t] - 1) e = Ts[t] - 1;
        g_se[t][q] = make_int2(s, e);
    }
}

__device__ __forceinline__ void red4(float* p, float4 v) {
    asm volatile("red.global.add.v4.f32 [%0], {%1, %2, %3, %4};"
                 :: "l"(p), "f"(v.x), "f"(v.y), "f"(v.z), "f"(v.w)
                 : "memory");
}

// Process one 32KB tile of one tensor: load to smem, scan queries of this batch,
// scatter partial sums with vectorized global reductions.
template<int TENSOR, int T, int C, int R, int CHOFF>
__device__ __forceinline__ void pool_tile(const float* __restrict__ v,
                                          float* __restrict__ out,
                                          float4* __restrict__ tile,
                                          int b, int tileIdx) {
    const int t0 = tileIdx * R;
    const int t1 = t0 + R;
    constexpr int VEC = C / 4;              // float4s per row
    constexpr int NV  = R * VEC;            // float4s per tile (2048)

    // --- Load tile (coalesced float4, 8 independent chains per thread) ---
    const float4* src = (const float4*)v + ((size_t)b * T + t0) * VEC;
#pragma unroll
    for (int i = threadIdx.x; i < NV; i += THREADS)
        tile[i] = __ldg(src + i);
    __syncthreads();

    // --- One warp per query; scan this batch's 512 queries ---
    const int warp = threadIdx.x >> 5;
    const int lane = threadIdx.x & 31;

    for (int qi = warp; qi < 512; qi += (THREADS / 32)) {
        const int q = b * 512 + qi;
        const int2 se = g_se[TENSOR][q];
        int lo = se.x > t0 ? se.x : t0;
        int hi = se.y < t1 ? se.y : t1;
        if (lo >= hi) continue;

        if (C == 128) {
            float4 acc = make_float4(0.f, 0.f, 0.f, 0.f);
            const float4* rowp = tile + (lo - t0) * VEC + lane;
            for (int r = lo; r < hi; r++, rowp += VEC) {
                float4 x = *rowp;
                acc.x += x.x; acc.y += x.y; acc.z += x.z; acc.w += x.w;
            }
            red4(out + (size_t)q * 512 + CHOFF + lane * 4, acc);
        } else {  // C == 256: each lane owns 2 float4s per row
            float4 a0 = make_float4(0.f, 0.f, 0.f, 0.f);
            float4 a1 = make_float4(0.f, 0.f, 0.f, 0.f);
            const float4* rowp = tile + (lo - t0) * VEC + lane;
            for (int r = lo; r < hi; r++, rowp += VEC) {
                float4 x = rowp[0];
                float4 y = rowp[32];
                a0.x += x.x; a0.y += x.y; a0.z += x.z; a0.w += x.w;
                a1.x += y.x; a1.y += y.y; a1.z += y.z; a1.w += y.w;
            }
            red4(out + (size_t)q * 512 + CHOFF + lane * 4,       a0);
            red4(out + (size_t)q * 512 + CHOFF + 128 + lane * 4, a1);
        }
    }
}

// Single fused kernel over all (tensor, batch, tile) triples.
// blocks [0,2048):    tensor0, 256 tiles x 8 batches (R=64,  C=128)
// blocks [2048,3072): tensor1, 128 tiles x 8 batches (R=64,  C=128)
// blocks [3072,4096): tensor2, 128 tiles x 8 batches (R=32,  C=256)
__global__ void __launch_bounds__(THREADS)
pool_kernel(const float* __restrict__ v0, const float* __restrict__ v1,
            const float* __restrict__ v2, float* __restrict__ out) {
    __shared__ float4 tile[2048];           // 32 KB
    const int blk = blockIdx.x;
    if (blk < 2048) {
        pool_tile<0, 16384, 128, 64, 0>(v0, out, tile, blk >> 8, blk & 255);
    } else if (blk < 3072) {
        const int i = blk - 2048;
        pool_tile<1, 8192, 128, 64, 128>(v1, out, tile, i >> 7, i & 127);
    } else {
        const int i = blk - 3072;
        pool_tile<2, 4096, 256, 32, 256>(v2, out, tile, i >> 7, i & 127);
    }
}

// Divide accumulated sums by count; empty ranges remain zero (from memset).
__global__ void __launch_bounds__(THREADS)
divide_kernel(float* __restrict__ out) {
    const int idx = blockIdx.x * blockDim.x + threadIdx.x;  // float4 index
    if (idx >= NQ * 128) return;
    const int q  = idx >> 7;
    const int c4 = idx & 127;
    const int tensor = (c4 < 32) ? 0 : (c4 < 64 ? 1 : 2);
    const int2 se = g_se[tensor][q];
    const int cnt = se.y - se.x;
    if (cnt > 0) {
        const float inv = 1.0f / (float)cnt;
        float4* p = (float4*)out + idx;
        float4 x = *p;
        x.x *= inv; x.y *= inv; x.z *= inv; x.w *= inv;
        *p = x;
    }
}

extern "C" void kernel_launch(void* const* d_in, const int* in_sizes, int n_in,
                              void* d_out, int out_size) {
    const float* v0 = (const float*)d_in[0];  // [8, 16384, 128]
    const float* v1 = (const float*)d_in[1];  // [8, 8192, 128]
    const float* v2 = (const float*)d_in[2];  // [8, 4096, 256]
    const float* st = (const float*)d_in[3];  // [8, 512]
    const float* du = (const float*)d_in[4];  // [8, 512]
    float* out = (float*)d_out;               // [8, 512, 512]

    cudaMemsetAsync(out, 0, (size_t)out_size * sizeof(float));
    precompute_se<<<(NQ + THREADS - 1) / THREADS, THREADS>>>(st, du);
    pool_kernel<<<4096, THREADS>>>(v0, v1, v2, out);
    divide_kernel<<<(NQ * 128 + THREADS - 1) / THREADS, THREADS>>>(out);
}

// round 5
// speedup vs baseline: 2.4622x; 2.4622x over previous
#include <cuda_runtime.h>
#include <cstdint>

#define THREADS 256
#define NQ 4096

// Chunk sums: 8 rows per chunk. [B][T/8][C]
__device__ float g_cs0[8][2048][128];   // tensor0: T=16384, C=128  (8 MB)
__device__ float g_cs1[8][1024][128];   // tensor1: T=8192,  C=128  (4 MB)
__device__ float g_cs2[8][512][256];    // tensor2: T=4096,  C=256  (4 MB)

__device__ __forceinline__ void add4(float4& a, const float4 x) {
    a.x += x.x; a.y += x.y; a.z += x.z; a.w += x.w;
}

// ---------------- K1: per-chunk sums ----------------
// One warp = one 8-row chunk. C=128: lane owns 1 float4/row; C=256: 2.
__global__ void __launch_bounds__(THREADS)
chunk_sum_kernel(const float* __restrict__ v0, const float* __restrict__ v1,
                 const float* __restrict__ v2) {
    const int blk  = blockIdx.x;
    const int warp = threadIdx.x >> 5;
    const int lane = threadIdx.x & 31;

    if (blk < 2048) {                       // tensor0: 256 blocks/batch
        const int b  = blk >> 8;
        const int ci = ((blk & 255) << 3) + warp;        // 0..2047
        const float4* src = (const float4*)v0 + ((size_t)b * 16384 + (ci << 3)) * 32 + lane;
        float4 a = make_float4(0.f, 0.f, 0.f, 0.f);
#pragma unroll
        for (int r = 0; r < 8; r++) add4(a, __ldg(src + r * 32));
        ((float4*)g_cs0)[(((b << 11) + ci) << 5) + lane] = a;
    } else if (blk < 3072) {                // tensor1: 128 blocks/batch
        const int i  = blk - 2048;
        const int b  = i >> 7;
        const int ci = ((i & 127) << 3) + warp;          // 0..1023
        const float4* src = (const float4*)v1 + ((size_t)b * 8192 + (ci << 3)) * 32 + lane;
        float4 a = make_float4(0.f, 0.f, 0.f, 0.f);
#pragma unroll
        for (int r = 0; r < 8; r++) add4(a, __ldg(src + r * 32));
        ((float4*)g_cs1)[(((b << 10) + ci) << 5) + lane] = a;
    } else {                                // tensor2: 64 blocks/batch, C=256
        const int i  = blk - 3072;
        const int b  = i >> 6;
        const int ci = ((i & 63) << 3) + warp;           // 0..511
        const float4* src = (const float4*)v2 + ((size_t)b * 4096 + (ci << 3)) * 64 + lane;
        float4 a0 = make_float4(0.f, 0.f, 0.f, 0.f);
        float4 a1 = make_float4(0.f, 0.f, 0.f, 0.f);
#pragma unroll
        for (int r = 0; r < 8; r++) {
            add4(a0, __ldg(src + r * 64));
            add4(a1, __ldg(src + r * 64 + 32));
        }
        float4* dst = ((float4*)g_cs2) + (((b << 9) + ci) << 6) + lane;
        dst[0]  = a0;
        dst[32] = a1;
    }
}

// ---------------- K2: per-query gather ----------------
template<int T, int VEC, int NCHUNK, int CHOFF, int NACC>
__device__ __forceinline__ void gather_one(
    const float* __restrict__ v, const float* __restrict__ cs,
    float* __restrict__ out, float ratio,
    const float* __restrict__ start, const float* __restrict__ dur,
    int q, int lane)
{
    const int b = q >> 9;
    const float st = start[q];
    const float du = dur[q];
    int s = (int)floorf(st * ratio);
    if (s > T - 1) s = T - 1;
    int e = (int)ceilf((st + du + 1e-3f) * ratio);
    if (e > T - 1) e = T - 1;
    const int cnt = e - s;

    float4 acc[NACC];
#pragma unroll
    for (int j = 0; j < NACC; j++) acc[j] = make_float4(0.f, 0.f, 0.f, 0.f);

    if (cnt > 0) {
        const float4* vb = (const float4*)v + (size_t)b * T * VEC + lane;
        const int cLo = (s + 7) >> 3;
        const int cHi = e >> 3;
        if (cLo <= cHi) {
            // interior chunks [cLo, cHi)
            const float4* cp = (const float4*)cs + ((size_t)b * NCHUNK + cLo) * VEC + lane;
            for (int k = cLo; k < cHi; k++, cp += VEC) {
#pragma unroll
                for (int j = 0; j < NACC; j++) add4(acc[j], __ldg(cp + j * 32));
            }
            // left edge [s, 8*cLo)
            for (int r = s; r < (cLo << 3); r++) {
#pragma unroll
                for (int j = 0; j < NACC; j++) add4(acc[j], __ldg(vb + (size_t)r * VEC + j * 32));
            }
            // right edge [8*cHi, e)
            for (int r = (cHi << 3); r < e; r++) {
#pragma unroll
                for (int j = 0; j < NACC; j++) add4(acc[j], __ldg(vb + (size_t)r * VEC + j * 32));
            }
        } else {
            // whole range inside one chunk
            for (int r = s; r < e; r++) {
#pragma unroll
                for (int j = 0; j < NACC; j++) add4(acc[j], __ldg(vb + (size_t)r * VEC + j * 32));
            }
        }
        const float inv = 1.0f / (float)cnt;
#pragma unroll
        for (int j = 0; j < NACC; j++) {
            acc[j].x *= inv; acc[j].y *= inv; acc[j].z *= inv; acc[j].w *= inv;
        }
    }
    float4* op = (float4*)(out + (size_t)q * 512 + CHOFF) + lane;
#pragma unroll
    for (int j = 0; j < NACC; j++) op[j * 32] = acc[j];
}

__global__ void __launch_bounds__(THREADS)
gather_kernel(const float* __restrict__ v0, const float* __restrict__ v1,
              const float* __restrict__ v2,
              const float* __restrict__ start, const float* __restrict__ dur,
              float* __restrict__ out)
{
    const int wg   = blockIdx.x * (THREADS / 32) + (threadIdx.x >> 5); // 0..12287
    const int lane = threadIdx.x & 31;
    const int tensor = wg >> 12;
    const int q      = wg & 4095;

    if (tensor == 0) {
        gather_one<16384, 32, 2048, 0, 1>(v0, (const float*)g_cs0, out, 1.0f,
                                          start, dur, q, lane);
    } else if (tensor == 1) {
        gather_one<8192, 32, 1024, 128, 1>(v1, (const float*)g_cs1, out, 0.5f,
                                           start, dur, q, lane);
    } else {
        gather_one<4096, 64, 512, 256, 2>(v2, (const float*)g_cs2, out, 0.25f,
                                          start, dur, q, lane);
    }
}

extern "C" void kernel_launch(void* const* d_in, const int* in_sizes, int n_in,
                              void* d_out, int out_size) {
    const float* v0 = (const float*)d_in[0];  // [8, 16384, 128]
    const float* v1 = (const float*)d_in[1];  // [8, 8192, 128]
    const float* v2 = (const float*)d_in[2];  // [8, 4096, 256]
    const float* st = (const float*)d_in[3];  // [8, 512]
    const float* du = (const float*)d_in[4];  // [8, 512]
    float* out = (float*)d_out;               // [8, 512, 512]

    chunk_sum_kernel<<<3584, THREADS>>>(v0, v1, v2);
    gather_kernel<<<12288 / (THREADS / 32), THREADS>>>(v0, v1, v2, st, du, out);
}